// round 9
// baseline (speedup 1.0000x reference)
#include <cuda_runtime.h>
#include <cstdint>

#define HDIM 4096
#define THREADS 256
#define NWARPS (THREADS / 32)
#define EPT (HDIM / THREADS)     // 16 elems per thread
#define VEC 4
#define NITER (EPT / VEC)        // 4
#define GRID 2048
#define EPSF 1e-6f

__global__ __launch_bounds__(THREADS) void qrmsnorm_pipe_kernel(
    const float* __restrict__ x,
    const float* __restrict__ w,
    float* __restrict__ q_out,
    float* __restrict__ scale_out,
    int n_rows)
{
    const int tid = threadIdx.x;

    __shared__ float s_sum[NWARPS];
    __shared__ float s_max[NWARPS];

    // Weight: load once, hold in registers for all rows.
    float wreg[EPT];
    #pragma unroll
    for (int i = 0; i < NITER; i++) {
        const int base = (i * THREADS + tid) * VEC;
        float4 wv = __ldg(reinterpret_cast<const float4*>(w + base));
        wreg[i * VEC + 0] = wv.x;
        wreg[i * VEC + 1] = wv.y;
        wreg[i * VEC + 2] = wv.z;
        wreg[i * VEC + 3] = wv.w;
    }

    // Prologue: load first row.
    int row = blockIdx.x;
    float cur[EPT];
    {
        const float* xr = x + (size_t)row * HDIM;
        #pragma unroll
        for (int i = 0; i < NITER; i++) {
            const int base = (i * THREADS + tid) * VEC;
            float4 xv = __ldcs(reinterpret_cast<const float4*>(xr + base));
            cur[i * VEC + 0] = xv.x;
            cur[i * VEC + 1] = xv.y;
            cur[i * VEC + 2] = xv.z;
            cur[i * VEC + 3] = xv.w;
        }
    }

    while (row < n_rows) {
        const int next_row = row + GRID;

        // Issue NEXT row's loads now — they stay in flight while we
        // reduce/quantize/store the current row (covers the store phase).
        float nxt[EPT];
        if (next_row < n_rows) {
            const float* xn = x + (size_t)next_row * HDIM;
            #pragma unroll
            for (int i = 0; i < NITER; i++) {
                const int base = (i * THREADS + tid) * VEC;
                float4 xv = __ldcs(reinterpret_cast<const float4*>(xn + base));
                nxt[i * VEC + 0] = xv.x;
                nxt[i * VEC + 1] = xv.y;
                nxt[i * VEC + 2] = xv.z;
                nxt[i * VEC + 3] = xv.w;
            }
        }

        // Process current row.
        float sumsq = 0.0f, maxa = 0.0f;
        float xw[EPT];
        #pragma unroll
        for (int e = 0; e < EPT; e++) {
            sumsq = fmaf(cur[e], cur[e], sumsq);
            float p = cur[e] * wreg[e];
            xw[e] = p;
            maxa = fmaxf(maxa, fabsf(p));
        }

        #pragma unroll
        for (int o = 16; o > 0; o >>= 1) {
            sumsq += __shfl_xor_sync(0xffffffffu, sumsq, o);
            maxa   = fmaxf(maxa, __shfl_xor_sync(0xffffffffu, maxa, o));
        }

        const int warp = tid >> 5;
        const int lane = tid & 31;
        __syncthreads();   // protect smem reuse from previous iteration
        if (lane == 0) { s_sum[warp] = sumsq; s_max[warp] = maxa; }
        __syncthreads();

        float total  = s_sum[0];
        float maxtot = s_max[0];
        #pragma unroll
        for (int k = 1; k < NWARPS; k++) {
            total  += s_sum[k];
            maxtot  = fmaxf(maxtot, s_max[k]);
        }

        const float rstd = rsqrtf(total * (1.0f / HDIM) + EPSF);
        if (tid == 0) scale_out[row] = rstd * maxtot * (1.0f / 127.0f);

        const float r = 127.0f / fmaxf(maxtot, 1e-30f);

        float* qr = q_out + (size_t)row * HDIM;
        #pragma unroll
        for (int i = 0; i < NITER; i++) {
            const int base = (i * THREADS + tid) * VEC;
            float4 o;
            float* ov = &o.x;
            #pragma unroll
            for (int j = 0; j < VEC; j++) {
                float v = rintf(xw[i * VEC + j] * r);
                ov[j] = fminf(fmaxf(v, -128.0f), 127.0f);
            }
            __stcs(reinterpret_cast<float4*>(qr + base), o);
        }

        // Rotate pipeline.
        if (next_row < n_rows) {
            #pragma unroll
            for (int e = 0; e < EPT; e++) cur[e] = nxt[e];
        }
        row = next_row;
    }
}

extern "C" void kernel_launch(void* const* d_in, const int* in_sizes, int n_in,
                              void* d_out, int out_size)
{
    const float* x = (const float*)d_in[0];   // hidden_states [B,S,H] (fp32)
    const float* w = (const float*)d_in[1];   // weight [H]

    const long long total_elems = (long long)in_sizes[0];    // B*S*H
    const int h = in_sizes[1];                                // H = 4096
    const int n_rows = (int)(total_elems / h);                // B*S = 16384

    float* q = (float*)d_out;                                 // output 0: q as fp32
    float* scale = (float*)d_out + ((long long)out_size - n_rows);

    qrmsnorm_pipe_kernel<<<GRID, THREADS>>>(x, w, q, scale, n_rows);
}

// round 10
// speedup vs baseline: 1.0284x; 1.0284x over previous
#include <cuda_runtime.h>
#include <cstdint>

#define HDIM 4096
#define THREADS 256
#define NWARPS (THREADS / 32)
#define ELEMS_PER_THREAD (HDIM / THREADS)   // 16
#define VEC 4                               // floats per float4
#define NITER (ELEMS_PER_THREAD / VEC)      // 4
#define EPSF 1e-6f

__global__ __launch_bounds__(THREADS) void qrmsnorm_kernel(
    const float* __restrict__ x,
    const float* __restrict__ w,
    float* __restrict__ q_out,      // quantized values emitted as float32
    float* __restrict__ scale_out)
{
    const int row = blockIdx.x;
    const float* xr = x + (size_t)row * HDIM;
    const int tid = threadIdx.x;

    float xw[ELEMS_PER_THREAD];
    float sumsq = 0.0f;
    float maxa  = 0.0f;

    // Single pass: streaming (non-temporal) x loads, cached weight loads.
    // Keep x*w in regs; jointly accumulate sum(x^2) and max|x*w|.
    #pragma unroll
    for (int i = 0; i < NITER; i++) {
        const int base = (i * THREADS + tid) * VEC;
        float4 xv = __ldcs(reinterpret_cast<const float4*>(xr + base));
        float4 wv = __ldg (reinterpret_cast<const float4*>(w  + base));
        const float* xf = &xv.x;
        const float* wf = &wv.x;
        #pragma unroll
        for (int j = 0; j < VEC; j++) {
            sumsq = fmaf(xf[j], xf[j], sumsq);
            float p = xf[j] * wf[j];
            xw[i * VEC + j] = p;
            maxa = fmaxf(maxa, fabsf(p));
        }
    }

    // Warp reduction of (sumsq, maxa).
    #pragma unroll
    for (int o = 16; o > 0; o >>= 1) {
        sumsq += __shfl_xor_sync(0xffffffffu, sumsq, o);
        maxa   = fmaxf(maxa, __shfl_xor_sync(0xffffffffu, maxa, o));
    }

    // Single-barrier block reduction: per-warp partials to smem, one sync,
    // then every thread reduces the NWARPS partials locally.
    __shared__ float s_sum[NWARPS];
    __shared__ float s_max[NWARPS];

    const int warp = tid >> 5;
    const int lane = tid & 31;
    if (lane == 0) { s_sum[warp] = sumsq; s_max[warp] = maxa; }
    __syncthreads();

    float total  = s_sum[0];
    float maxtot = s_max[0];
    #pragma unroll
    for (int k = 1; k < NWARPS; k++) {
        total  += s_sum[k];
        maxtot  = fmaxf(maxtot, s_max[k]);
    }

    const float rstd  = rsqrtf(total * (1.0f / HDIM) + EPSF);
    const float scale = rstd * maxtot * (1.0f / 127.0f);
    if (tid == 0) scale_out[row] = scale;

    // q = clip(round(x*w*rstd / scale)) = clip(round(x*w * 127/max|x*w|))
    const float r = 127.0f / fmaxf(maxtot, 1e-30f);

    float* qr = q_out + (size_t)row * HDIM;
    #pragma unroll
    for (int i = 0; i < NITER; i++) {
        const int base = (i * THREADS + tid) * VEC;
        float4 o;
        float* ov = &o.x;
        #pragma unroll
        for (int j = 0; j < VEC; j++) {
            float v = rintf(xw[i * VEC + j] * r);
            ov[j] = fminf(fmaxf(v, -128.0f), 127.0f);
        }
        __stcs(reinterpret_cast<float4*>(qr + base), o);
    }
}

extern "C" void kernel_launch(void* const* d_in, const int* in_sizes, int n_in,
                              void* d_out, int out_size)
{
    const float* x = (const float*)d_in[0];   // hidden_states [B,S,H] (fp32)
    const float* w = (const float*)d_in[1];   // weight [H]

    const long long total_elems = (long long)in_sizes[0];    // B*S*H
    const int h = in_sizes[1];                                // H = 4096
    const int n_rows = (int)(total_elems / h);                // B*S = 16384

    float* q = (float*)d_out;                                 // output 0: q as fp32
    // output 1: per-token scales, last n_rows float32 elements of d_out
    float* scale = (float*)d_out + ((long long)out_size - n_rows);

    qrmsnorm_kernel<<<n_rows, THREADS>>>(x, w, q, scale);
}

// round 11
// speedup vs baseline: 1.0332x; 1.0047x over previous
#include <cuda_runtime.h>
#include <cstdint>

#define HDIM 4096
#define THREADS 256
#define NWARPS (THREADS / 32)
#define ELEMS_PER_THREAD (HDIM / THREADS)   // 16
#define VEC 4                               // floats per float4
#define NITER (ELEMS_PER_THREAD / VEC)      // 4
#define EPSF 1e-6f

__global__ __launch_bounds__(THREADS) void qrmsnorm_kernel(
    const float* __restrict__ x,
    const float* __restrict__ w,
    float* __restrict__ q_out,      // quantized values emitted as float32
    float* __restrict__ scale_out)
{
    const int row = blockIdx.x;
    const float* xr = x + (size_t)row * HDIM;
    const int tid = threadIdx.x;

    float xw[ELEMS_PER_THREAD];
    float sumsq = 0.0f;
    float maxa  = 0.0f;

    // Single pass: streaming (non-temporal) x loads, cached weight loads.
    // Keep x*w in regs; jointly accumulate sum(x^2) and max|x*w|.
    #pragma unroll
    for (int i = 0; i < NITER; i++) {
        const int base = (i * THREADS + tid) * VEC;
        float4 xv = __ldcs(reinterpret_cast<const float4*>(xr + base));
        float4 wv = __ldg (reinterpret_cast<const float4*>(w  + base));
        const float* xf = &xv.x;
        const float* wf = &wv.x;
        #pragma unroll
        for (int j = 0; j < VEC; j++) {
            sumsq = fmaf(xf[j], xf[j], sumsq);
            float p = xf[j] * wf[j];
            xw[i * VEC + j] = p;
            maxa = fmaxf(maxa, fabsf(p));
        }
    }

    // Warp reduction of (sumsq, maxa).
    #pragma unroll
    for (int o = 16; o > 0; o >>= 1) {
        sumsq += __shfl_xor_sync(0xffffffffu, sumsq, o);
        maxa   = fmaxf(maxa, __shfl_xor_sync(0xffffffffu, maxa, o));
    }

    // Single-barrier block reduction: per-warp partials to smem, one sync,
    // then every thread reduces the NWARPS partials locally.
    __shared__ float s_sum[NWARPS];
    __shared__ float s_max[NWARPS];

    const int warp = tid >> 5;
    const int lane = tid & 31;
    if (lane == 0) { s_sum[warp] = sumsq; s_max[warp] = maxa; }
    __syncthreads();

    float total  = s_sum[0];
    float maxtot = s_max[0];
    #pragma unroll
    for (int k = 1; k < NWARPS; k++) {
        total  += s_sum[k];
        maxtot  = fmaxf(maxtot, s_max[k]);
    }

    const float rstd  = rsqrtf(total * (1.0f / HDIM) + EPSF);
    const float scale = rstd * maxtot * (1.0f / 127.0f);
    if (tid == 0) scale_out[row] = scale;

    // q = clip(round(x*w*rstd / scale)) = clip(round(x*w * 127/max|x*w|))
    const float r = 127.0f / fmaxf(maxtot, 1e-30f);

    float* qr = q_out + (size_t)row * HDIM;
    #pragma unroll
    for (int i = 0; i < NITER; i++) {
        const int base = (i * THREADS + tid) * VEC;
        float4 o;
        float* ov = &o.x;
        #pragma unroll
        for (int j = 0; j < VEC; j++) {
            float v = rintf(xw[i * VEC + j] * r);
            ov[j] = fminf(fmaxf(v, -128.0f), 127.0f);
        }
        __stcs(reinterpret_cast<float4*>(qr + base), o);
    }
}

extern "C" void kernel_launch(void* const* d_in, const int* in_sizes, int n_in,
                              void* d_out, int out_size)
{
    const float* x = (const float*)d_in[0];   // hidden_states [B,S,H] (fp32)
    const float* w = (const float*)d_in[1];   // weight [H]

    const long long total_elems = (long long)in_sizes[0];    // B*S*H
    const int h = in_sizes[1];                                // H = 4096
    const int n_rows = (int)(total_elems / h);                // B*S = 16384

    float* q = (float*)d_out;                                 // output 0: q as fp32
    // output 1: per-token scales, last n_rows float32 elements of d_out
    float* scale = (float*)d_out + ((long long)out_size - n_rows);

    qrmsnorm_kernel<<<n_rows, THREADS>>>(x, w, q, scale);
}